// round 1
// baseline (speedup 1.0000x reference)
#include <cuda_runtime.h>
#include <cstdint>

#define BB 8
#define CC 20
#define NN 2048
#define THREADS 512
#define NMS_T 0.45f
#define PRE_T 0.005f

// dynamic shared layout:
//   uint64 keys[2048]   (16384 B)  : (conf_bits<<32)|(2047-idx), sorted desc
//   float  sx1..sy2[2048] (4*8192) : sorted boxes SoA
//   float  sar[2048]     (8192 B)  : areas
//   uint32 skeep[64]     (256 B)   : keep bitmap
// total 57600 B -> needs opt-in dynamic smem > 48KB
extern __shared__ unsigned char smem_raw[];

__global__ __launch_bounds__(THREADS, 2)
void nms_kernel(const float* __restrict__ bbs, const float* __restrict__ conf,
                float* __restrict__ out) {
    const int bc = blockIdx.x;
    const int b = bc / CC;
    const int c = bc % CC;
    const int tid = threadIdx.x;

    unsigned long long* keys = (unsigned long long*)smem_raw;
    float* sx1 = (float*)(keys + NN);
    float* sy1 = sx1 + NN;
    float* sx2 = sy1 + NN;
    float* sy2 = sx2 + NN;
    float* sar = sy2 + NN;
    unsigned* skeep = (unsigned*)(sar + NN);

    // ---- load conf, pack keys ----
    const float* confp = conf + ((size_t)b * CC + c) * NN;
    for (int i = tid; i < NN; i += THREADS) {
        unsigned fb = __float_as_uint(confp[i]);
        keys[i] = ((unsigned long long)fb << 32) | (unsigned)(NN - 1 - i);
    }
    __syncthreads();

    // ---- bitonic sort, descending ----
    for (int k = 2; k <= NN; k <<= 1) {
        for (int j = k >> 1; j > 0; j >>= 1) {
            for (int i = tid; i < NN; i += THREADS) {
                int ixj = i ^ j;
                if (ixj > i) {
                    unsigned long long a = keys[i];
                    unsigned long long bkey = keys[ixj];
                    bool firstHalf = ((i & k) == 0);  // descending in first half
                    bool swap = firstHalf ? (a < bkey) : (a > bkey);
                    if (swap) { keys[i] = bkey; keys[ixj] = a; }
                }
            }
            __syncthreads();
        }
    }

    // ---- gather boxes in sorted order (SoA), compute areas ----
    const float4* boxp = (const float4*)(bbs + (size_t)b * NN * 4);
    for (int i = tid; i < NN; i += THREADS) {
        unsigned long long key = keys[i];
        int j = NN - 1 - (int)(unsigned)(key & 0xffffffffu);
        float4 bx = boxp[j];
        sx1[i] = bx.x; sy1[i] = bx.y; sx2[i] = bx.z; sy2[i] = bx.w;
        sar[i] = fmaxf(bx.z - bx.x, 0.0f) * fmaxf(bx.w - bx.y, 0.0f);
    }

    // ---- init keep bitmap: conf_sorted > PRE_T ----
    for (int i = tid; i < NN; i += THREADS) {
        float cf = __uint_as_float((unsigned)(keys[i] >> 32));
        unsigned m = __ballot_sync(0xffffffffu, cf > PRE_T);
        if ((tid & 31) == 0) skeep[i >> 5] = m;
    }
    __syncthreads();

    // ---- greedy sequential NMS ----
    int need_sync = 0;
    for (int i = 0; i < NN - 1; ++i) {
        if (need_sync) __syncthreads();
        bool alive = (skeep[i >> 5] >> (i & 31)) & 1;  // uniform across block
        need_sync = alive;
        if (!alive) continue;
        float px1 = sx1[i], py1 = sy1[i], px2 = sx2[i], py2 = sy2[i];
        float pa = sar[i];
        for (int j = i + 1 + tid; j < NN; j += THREADS) {
            unsigned kw = skeep[j >> 5];
            if (!((kw >> (j & 31)) & 1)) continue;  // already dead: skip math
            float iw = fminf(px2, sx2[j]) - fmaxf(px1, sx1[j]);
            float ih = fminf(py2, sy2[j]) - fmaxf(py1, sy1[j]);
            iw = fmaxf(iw, 0.0f);
            ih = fmaxf(ih, 0.0f);
            float inter = iw * ih;
            float den = fmaxf(pa + sar[j] - inter, 1e-12f);
            float iou = inter / den;  // IEEE div.rn to match reference rounding
            if (iou > NMS_T) {
                atomicAnd(&skeep[j >> 5], ~(1u << (j & 31)));
            }
        }
    }
    __syncthreads();

    // ---- scatter back to original order ----
    float* outp = out + ((size_t)b * CC + c) * NN;
    for (int i = tid; i < NN; i += THREADS) {
        unsigned long long key = keys[i];
        int j = NN - 1 - (int)(unsigned)(key & 0xffffffffu);
        bool alive = (skeep[i >> 5] >> (i & 31)) & 1;
        outp[j] = alive ? __uint_as_float((unsigned)(key >> 32)) : 0.0f;
    }
}

extern "C" void kernel_launch(void* const* d_in, const int* in_sizes, int n_in,
                              void* d_out, int out_size) {
    // Identify inputs by size (bbs: 8*2048*4 = 65536, conf: 8*20*2048 = 327680)
    const float* bbs;
    const float* conf;
    if (in_sizes[0] == BB * NN * 4) {
        bbs = (const float*)d_in[0];
        conf = (const float*)d_in[1];
    } else {
        bbs = (const float*)d_in[1];
        conf = (const float*)d_in[0];
    }
    float* out = (float*)d_out;

    const size_t smem = NN * 8            // keys
                      + 5 * NN * 4        // boxes + area
                      + 64 * 4;           // keep bitmap
    cudaFuncSetAttribute(nms_kernel, cudaFuncAttributeMaxDynamicSharedMemorySize,
                         (int)smem);
    nms_kernel<<<BB * CC, THREADS, smem>>>(bbs, conf, out);
}

// round 2
// speedup vs baseline: 29.7510x; 29.7510x over previous
#include <cuda_runtime.h>
#include <cstdint>

#define BB 8
#define CC 20
#define NN 2048
#define NMS_T 0.45f
#define PRE_T 0.005f
#define EDGE_CAP 262144
#define PAIR_CTAS 64

// Class-independent geometric suppression graph, per batch.
__device__ unsigned g_edges[BB][EDGE_CAP];
__device__ int g_cnt[BB];

__global__ void zero_kernel() {
    if (threadIdx.x < BB) g_cnt[threadIdx.x] = 0;
}

// ---- Kernel A: enumerate pairs with IoU > NMS_T (geometry only) ----
__global__ __launch_bounds__(256)
void pairs_kernel(const float* __restrict__ bbs) {
    __shared__ float4 sbox[NN];
    __shared__ float sarea[NN];
    const int b = blockIdx.y;
    const int tid = threadIdx.x;

    const float4* gb = (const float4*)(bbs + (size_t)b * NN * 4);
    for (int i = tid; i < NN; i += 256) {
        float4 v = gb[i];
        sbox[i] = v;
        sarea[i] = __fmul_rn(fmaxf(__fsub_rn(v.z, v.x), 0.0f),
                             fmaxf(__fsub_rn(v.w, v.y), 0.0f));
    }
    __syncthreads();

    int* cnt = &g_cnt[b];
    unsigned* el = g_edges[b];

    // rows strided across CTAs -> balanced triangle
    for (int i = blockIdx.x; i < NN - 1; i += PAIR_CTAS) {
        float4 p = sbox[i];          // broadcast
        float pa = sarea[i];
        for (int j = i + 1 + tid; j < NN; j += 256) {
            float4 q = sbox[j];
            float iw = __fsub_rn(fminf(p.z, q.z), fmaxf(p.x, q.x));
            if (iw <= 0.0f) continue;
            float ih = __fsub_rn(fminf(p.w, q.w), fmaxf(p.y, q.y));
            if (ih <= 0.0f) continue;
            float inter = __fmul_rn(iw, ih);
            float den = fmaxf(__fsub_rn(__fadd_rn(pa, sarea[j]), inter), 1e-12f);
            if (__fdiv_rn(inter, den) > NMS_T) {
                int idx = atomicAdd(cnt, 1);
                if (idx < EDGE_CAP)
                    el[idx] = ((unsigned)i << 11) | (unsigned)j;
            }
        }
    }
}

// ---- Kernel B: per-class fixpoint resolution over sparse edge list ----
__global__ __launch_bounds__(256)
void resolve_kernel(const float* __restrict__ conf, float* __restrict__ out) {
    __shared__ unsigned cb[NN];            // conf bits (monotone key, conf >= 0)
    __shared__ unsigned keep0m[64];        // pre-threshold bitmap
    __shared__ unsigned aliveA[64], aliveB[64], supp[64];
    __shared__ int changed;

    const int bc = blockIdx.x;
    const int b = bc / CC;
    const int tid = threadIdx.x;

    const float* cp = conf + (size_t)bc * NN;
    for (int i = tid; i < NN; i += 256) {
        float v = cp[i];
        cb[i] = __float_as_uint(v);
        unsigned m = __ballot_sync(0xffffffffu, v > PRE_T);
        if ((tid & 31) == 0) { keep0m[i >> 5] = m; aliveA[i >> 5] = m; }
    }
    __syncthreads();

    int E = g_cnt[b];
    if (E > EDGE_CAP) E = EDGE_CAP;
    const unsigned* el = g_edges[b];

    unsigned* cur = aliveA;
    unsigned* nxt = aliveB;

    for (int round = 0; round < NN; ++round) {
        __syncthreads();  // protect previous round's 'changed' read vs reset
        if (tid < 64) supp[tid] = 0;
        if (tid == 0) changed = 0;
        __syncthreads();

        for (int e = tid; e < E; e += 256) {
            unsigned u = el[e];
            int i = (int)(u >> 11), j = (int)(u & 2047u);
            unsigned bi = cb[i], bj = cb[j];
            int hi, lo;
            // stable-argsort tie rule: equal conf -> lower index ranks higher
            if (bi > bj || (bi == bj && i < j)) { hi = i; lo = j; }
            else                                { hi = j; lo = i; }
            if ((cur[hi >> 5] >> (hi & 31)) & 1u)
                atomicOr(&supp[lo >> 5], 1u << (lo & 31));
        }
        __syncthreads();

        if (tid < 64) {
            unsigned na = keep0m[tid] & ~supp[tid];
            nxt[tid] = na;
            if (na != cur[tid]) changed = 1;   // benign race: all write 1
        }
        __syncthreads();

        int ch = changed;
        unsigned* t = cur; cur = nxt; nxt = t;
        if (!ch) break;
    }

    float* op = out + (size_t)bc * NN;
    for (int i = tid; i < NN; i += 256) {
        bool a = (cur[i >> 5] >> (i & 31)) & 1u;
        op[i] = a ? __uint_as_float(cb[i]) : 0.0f;
    }
}

extern "C" void kernel_launch(void* const* d_in, const int* in_sizes, int n_in,
                              void* d_out, int out_size) {
    const float* bbs;
    const float* conf;
    if (in_sizes[0] == BB * NN * 4) {
        bbs = (const float*)d_in[0];
        conf = (const float*)d_in[1];
    } else {
        bbs = (const float*)d_in[1];
        conf = (const float*)d_in[0];
    }
    float* out = (float*)d_out;

    zero_kernel<<<1, 32>>>();
    pairs_kernel<<<dim3(PAIR_CTAS, BB), 256>>>(bbs);
    resolve_kernel<<<BB * CC, 256>>>(conf, out);
}